// round 1
// baseline (speedup 1.0000x reference)
#include <cuda_runtime.h>

#define H 1024
#define W 1024
#define PLANES 24            // 8 * 3
#define TH 16                // tile rows per block
#define TW 128               // tile cols per block
#define RE 8                 // elements per thread (columns)
#define BX 16                // threads in x  (BX*RE == TW)
#define BY 16                // threads in y  (BY == TH)
#define SROWS (TH + 3)       // 19 (rows i..i+3 needed, k in 0..3 only)
#define SCOLS (TW + 8)       // 136: cols [tile_x-4, tile_x+132)
#define NBX (W / TW)         // 8
#define NBY (H / TH)         // 64
#define NBLOCKS (NBX * NBY * PLANES)  // 12288

__device__ float g_partials[NBLOCKS];

__device__ __forceinline__ void load16(float* w, const float* p) {
#pragma unroll
    for (int q = 0; q < 4; q++) {
        float4 v = *reinterpret_cast<const float4*>(p + 4 * q);
        w[4 * q + 0] = v.x;
        w[4 * q + 1] = v.y;
        w[4 * q + 2] = v.z;
        w[4 * q + 3] = v.w;
    }
}

__global__ __launch_bounds__(BX* BY) void btv_kernel(const float* __restrict__ x) {
    __shared__ float s[SROWS][SCOLS];
    __shared__ float warp_sums[(BX * BY) / 32];

    const int tx = threadIdx.x;
    const int ty = threadIdx.y;
    const int tid = ty * BX + tx;

    const int tile_x = blockIdx.x * TW;
    const int tile_y = blockIdx.y * TH;
    const float* plane = x + (size_t)blockIdx.z * (H * W);

    // Cooperative load of (TH+3) x (TW+8) tile with circular wrap.
    // shared col c maps to global col (tile_x + c - 4) & (W-1)
    for (int idx = tid; idx < SROWS * SCOLS; idx += BX * BY) {
        int r = idx / SCOLS;
        int c = idx - r * SCOLS;
        int gr = (tile_y + r) & (H - 1);
        int gc = (tile_x + c - 4) & (W - 1);
        s[r][c] = plane[gr * W + gc];
    }
    __syncthreads();

    // This thread's 8 elements: global cols j0 = tile_x + tx*8 .. +7, row tile_y+ty.
    // Shared col of j0 is tx*8 + 4; register window covers shared cols [tx*8, tx*8+16).
    float acc = 0.0f;
    float c0[8];

    {
        float w0[16];
        load16(w0, &s[ty][tx * RE]);
#pragma unroll
        for (int e = 0; e < 8; e++) c0[e] = w0[4 + e];
        // k = 0, l = 1..3 (symmetry gives l = -1..-3)
#pragma unroll
        for (int l = 1; l <= 3; l++) {
#pragma unroll
            for (int e = 0; e < 8; e++) acc += fabsf(c0[e] - w0[4 + e + l]);
        }
    }

#pragma unroll
    for (int k = 1; k <= 3; k++) {
        float w[16];
        load16(w, &s[ty + k][tx * RE]);
#pragma unroll
        for (int dl = -3; dl <= 3; dl++) {
#pragma unroll
            for (int e = 0; e < 8; e++) acc += fabsf(c0[e] - w[4 + e + dl]);
        }
    }

    // Warp reduction (deterministic within warp)
#pragma unroll
    for (int o = 16; o > 0; o >>= 1) acc += __shfl_down_sync(0xFFFFFFFFu, acc, o);

    const int lane = tid & 31;
    const int wid = tid >> 5;
    if (lane == 0) warp_sums[wid] = acc;
    __syncthreads();

    if (tid == 0) {
        float bsum = 0.0f;
#pragma unroll
        for (int i = 0; i < (BX * BY) / 32; i++) bsum += warp_sums[i];
        int bidx = (blockIdx.z * gridDim.y + blockIdx.y) * gridDim.x + blockIdx.x;
        g_partials[bidx] = bsum;
    }
}

__global__ void btv_reduce_kernel(float* __restrict__ out) {
    __shared__ double sm[256];
    double t = 0.0;
    for (int i = threadIdx.x; i < NBLOCKS; i += 256) t += (double)g_partials[i];
    sm[threadIdx.x] = t;
    __syncthreads();
#pragma unroll
    for (int stride = 128; stride > 0; stride >>= 1) {
        if (threadIdx.x < stride) sm[threadIdx.x] += sm[threadIdx.x + stride];
        __syncthreads();
    }
    if (threadIdx.x == 0) {
        // factor 2 from (k,l) <-> (-k,-l) symmetry; WEIGHT=0.1; N = 8*3*1024*1024
        out[0] = (float)(sm[0] * (0.2 / 25165824.0));
    }
}

extern "C" void kernel_launch(void* const* d_in, const int* in_sizes, int n_in,
                              void* d_out, int out_size) {
    (void)in_sizes; (void)n_in; (void)out_size;
    const float* x = (const float*)d_in[0];
    float* out = (float*)d_out;

    dim3 grid(NBX, NBY, PLANES);
    dim3 block(BX, BY);
    btv_kernel<<<grid, block>>>(x);
    btv_reduce_kernel<<<1, 256>>>(out);
}